// round 5
// baseline (speedup 1.0000x reference)
#include <cuda_runtime.h>
#include <math.h>

#define NN      4096
#define DD      128
#define SPCC    8
#define NEGK    (NN - SPCC)
#define APB     8            // anchors per block
#define NBLK    (NN / APB)   // 512
#define NTHR    512
#define EPT     8            // elements per thread in the sort (NN/NTHR)
#define A_ALPHA 10.0f
#define A_BETA  2.0f
#define A_BASE  0.5f

#define NEGINF  (__int_as_float(0xff800000))

typedef unsigned long long ull;

// -------- device scratch (no dynamic allocation allowed) --------
__device__ float g_XT[DD * NN];    // transposed inputs: XT[d*NN + j] = X[j*DD + d]
__device__ int   g_aoff[NN];       // exclusive cumsum of (ap+an)
__device__ float g_loss[NN];
__device__ int   g_cnt[NN];
__device__ float g_stats[2];       // [0]=mean_pos_sim, [1]=mean_neg_sim (last anchor)

struct Tail {
    float pos[APB][16];
    int   poscnt[APB];
    int   ti[APB];
    int   ap[APB];
    int   an[APB];
    int   aoff[APB];
    float negsum[APB];
};

// smem: neg[APB*NN] | xsP[DD*APB] (packed f32x2) | red[NTHR] | Tail  (~138 KB)
#define SMEM_BYTES (APB*NN*4 + DD*APB*8 + NTHR*4 + (((int)sizeof(Tail) + 127) & ~127))

// ---- f32x2 packed helpers ----
__device__ __forceinline__ ull pk2(float lo, float hi) {
    ull r; asm("mov.b64 %0, {%1, %2};" : "=l"(r) : "f"(lo), "f"(hi)); return r;
}
__device__ __forceinline__ void upk2(float& lo, float& hi, ull v) {
    asm("mov.b64 {%0, %1}, %2;" : "=f"(lo), "=f"(hi) : "l"(v));
}
__device__ __forceinline__ ull fma2(ull a, ull b, ull c) {
    ull d; asm("fma.rn.f32x2 %0, %1, %2, %3;" : "=l"(d) : "l"(a), "l"(b), "l"(c)); return d;
}

// ---------------- transpose kernel ----------------
__global__ void transpose_kernel(const float* __restrict__ X) {
    __shared__ float tile[32][33];
    int tx = threadIdx.x, ty = threadIdx.y;
    #pragma unroll
    for (int q = 0; q < 4; q++) {
        int row = ty + q * 8;                 // local j
        int j = blockIdx.x * 32 + row;
        int d = blockIdx.y * 32 + tx;
        tile[row][tx] = X[j * DD + d];
    }
    __syncthreads();
    #pragma unroll
    for (int q = 0; q < 4; q++) {
        int row = ty + q * 8;                 // local d
        int d = blockIdx.y * 32 + row;
        int j = blockIdx.x * 32 + tx;
        g_XT[d * NN + j] = tile[tx][row];
    }
}

// ---------------- exclusive-scan kernel (offsets a[i]) ----------------
__global__ void scan_kernel(const int* __restrict__ ap, const int* __restrict__ an) {
    __shared__ int csum[1024];
    int t = threadIdx.x;
    int base = t * 4;
    int v[4]; int s = 0;
    #pragma unroll
    for (int k = 0; k < 4; k++) { v[k] = ap[base + k] + an[base + k]; s += v[k]; }
    csum[t] = s;
    __syncthreads();
    for (int off = 1; off < 1024; off <<= 1) {
        int add = (t >= off) ? csum[t - off] : 0;
        __syncthreads();
        csum[t] += add;
        __syncthreads();
    }
    int run = (t > 0) ? csum[t - 1] : 0;
    #pragma unroll
    for (int k = 0; k < 4; k++) { g_aoff[base + k] = run; run += v[k]; }
}

// ---------------- block reduce ----------------
__device__ __forceinline__ float block_reduce_sum(float v, float* red) {
    int t = threadIdx.x;
    red[t] = v;
    __syncthreads();
    for (int s = NTHR / 2; s > 0; s >>= 1) {
        if (t < s) red[t] += red[t + s];
        __syncthreads();
    }
    float r = red[0];
    __syncthreads();
    return r;
}

// compare-exchange in registers
__device__ __forceinline__ void ce(float* v, int i, int j, bool up) {
    float a = v[i], b = v[j];
    if ((a > b) == up) { v[i] = b; v[j] = a; }
}

// ---------------- main per-anchor kernel ----------------
__global__ void __launch_bounds__(NTHR, 1)
anchor_kernel(const float* __restrict__ X, const float* __restrict__ margin,
              const float* __restrict__ W, const int* __restrict__ targets,
              const int* __restrict__ ap, const int* __restrict__ an, int wtotal)
{
    extern __shared__ char sraw[];
    float* neg = (float*)sraw;                          // APB*NN floats
    ull*   xsP = (ull*)(neg + APB * NN);                // DD*APB packed (x,x)
    float* red = (float*)(xsP + DD * APB);              // NTHR floats
    Tail*  Tl  = (Tail*)(red + NTHR);

    int t  = threadIdx.x;
    int i0 = blockIdx.x * APB;

    if (t < APB) {
        int i = i0 + t;
        Tl->poscnt[t] = 0;
        Tl->ti[t]     = targets[i];
        Tl->ap[t]     = ap[i];
        Tl->an[t]     = an[i];
        Tl->aoff[t]   = g_aoff[i];
    }
    // build packed anchor matrix: xsP[d*APB + a] = (x, x)
    for (int idx = t; idx < APB * DD; idx += NTHR) {
        int a = idx / DD, d = idx % DD;
        float x = X[(i0 + a) * DD + d];
        xsP[d * APB + a] = pk2(x, x);
    }
    __syncthreads();

    int tis[APB];
    #pragma unroll
    for (int a = 0; a < APB; a++) tis[a] = Tl->ti[a];

    // ---- dot phase: each thread handles 2 groups of 4 contiguous j's ----
    #pragma unroll
    for (int h = 0; h < 2; h++) {
        int jb = h * (NN / 2) + t * 4;       // 16B-aligned
        ull acc2[APB][2];
        #pragma unroll
        for (int a = 0; a < APB; a++) { acc2[a][0] = 0ull; acc2[a][1] = 0ull; }

        #pragma unroll 4
        for (int d = 0; d < DD; d++) {
            float4 r4 = *(const float4*)(g_XT + d * NN + jb);   // LDG.128
            ull rlo = pk2(r4.x, r4.y);
            ull rhi = pk2(r4.z, r4.w);
            const ull* xp = xsP + d * APB;
            #pragma unroll
            for (int a = 0; a < APB; a++) {
                ull xa = xp[a];                                  // LDS broadcast
                acc2[a][0] = fma2(xa, rlo, acc2[a][0]);
                acc2[a][1] = fma2(xa, rhi, acc2[a][1]);
            }
        }

        int4 tj4 = *(const int4*)(targets + jb);
        int tja[4] = {tj4.x, tj4.y, tj4.z, tj4.w};
        #pragma unroll
        for (int a = 0; a < APB; a++) {
            float sv[4];
            upk2(sv[0], sv[1], acc2[a][0]);
            upk2(sv[2], sv[3], acc2[a][1]);
            #pragma unroll
            for (int q = 0; q < 4; q++) {
                if (tja[q] == tis[a]) {
                    float sim = sv[q];
                    sv[q] = NEGINF;
                    if (sim < 1.0f) {
                        int p = atomicAdd(&Tl->poscnt[a], 1);
                        if (p < 16) Tl->pos[a][p] = sim;
                    }
                }
            }
            *(float4*)(neg + a * NN + jb) = make_float4(sv[0], sv[1], sv[2], sv[3]);
        }
    }
    __syncthreads();

    // =========== bitonic sort (ascending), register-fused ===========
    int base = t * EPT;                 // this thread's 8-element chunk

    // -- session: kk = 2, 4, 8 entirely in registers --
    #pragma unroll
    for (int a = 0; a < APB; a++) {
        float* arr = neg + a * NN + base;
        float v[EPT];
        *(float4*)(v)     = *(float4*)(arr);
        *(float4*)(v + 4) = *(float4*)(arr + 4);
        // kk=2, jj=1 : up = ((idx & 2) == 0)
        ce(v, 0, 1, true);  ce(v, 2, 3, false);
        ce(v, 4, 5, true);  ce(v, 6, 7, false);
        // kk=4 : up = ((idx & 4) == 0)
        ce(v, 0, 2, true);  ce(v, 1, 3, true);
        ce(v, 4, 6, false); ce(v, 5, 7, false);
        ce(v, 0, 1, true);  ce(v, 2, 3, true);
        ce(v, 4, 5, false); ce(v, 6, 7, false);
        // kk=8 : up = ((base & 8) == 0)
        bool u8 = ((base & 8) == 0);
        ce(v, 0, 4, u8); ce(v, 1, 5, u8); ce(v, 2, 6, u8); ce(v, 3, 7, u8);
        ce(v, 0, 2, u8); ce(v, 1, 3, u8); ce(v, 4, 6, u8); ce(v, 5, 7, u8);
        ce(v, 0, 1, u8); ce(v, 2, 3, u8); ce(v, 4, 5, u8); ce(v, 6, 7, u8);
        *(float4*)(arr)     = *(float4*)(v);
        *(float4*)(arr + 4) = *(float4*)(v + 4);
    }
    __syncthreads();

    // -- kk = 16 .. NN --
    for (int kk = 16; kk <= NN; kk <<= 1) {
        // smem passes for jj >= 8 (pair enumeration: all lanes active)
        for (int jj = kk >> 1; jj >= 8; jj >>= 1) {
            int lowmask = jj - 1;
            #pragma unroll
            for (int a = 0; a < APB; a++) {
                float* arr = neg + a * NN;
                #pragma unroll
                for (int it = 0; it < (NN / 2) / NTHR; it++) {
                    int p = t + it * NTHR;
                    int idx = ((p & ~lowmask) << 1) | (p & lowmask);
                    int prt = idx | jj;
                    bool up = ((idx & kk) == 0);
                    float v0 = arr[idx], v1 = arr[prt];
                    if ((v0 > v1) == up) { arr[idx] = v1; arr[prt] = v0; }
                }
            }
            __syncthreads();
        }
        // register session for jj = 4, 2, 1 (uniform direction per chunk)
        bool up = ((base & kk) == 0);
        #pragma unroll
        for (int a = 0; a < APB; a++) {
            float* arr = neg + a * NN + base;
            float v[EPT];
            *(float4*)(v)     = *(float4*)(arr);
            *(float4*)(v + 4) = *(float4*)(arr + 4);
            ce(v, 0, 4, up); ce(v, 1, 5, up); ce(v, 2, 6, up); ce(v, 3, 7, up);
            ce(v, 0, 2, up); ce(v, 1, 3, up); ce(v, 4, 6, up); ce(v, 5, 7, up);
            ce(v, 0, 1, up); ce(v, 2, 3, up); ce(v, 4, 5, up); ce(v, 6, 7, up);
            *(float4*)(arr)     = *(float4*)(v);
            *(float4*)(arr + 4) = *(float4*)(v + 4);
        }
        __syncthreads();
    }

    // ---- per-anchor: sort the (<=8, capped 16) positives ----
    if (t < APB) {
        int cnt = Tl->poscnt[t]; if (cnt > 16) cnt = 16;
        float pv[16];
        for (int q = 0; q < cnt; q++) pv[q] = Tl->pos[t][q];
        for (int q = 1; q < cnt; q++) {
            float key = pv[q]; int r = q - 1;
            while (r >= 0 && pv[r] > key) { pv[r + 1] = pv[r]; r--; }
            pv[r + 1] = key;
        }
        for (int q = 0; q < cnt; q++) Tl->pos[t][q] = pv[q];
        Tl->poscnt[t] = cnt;
    }
    __syncthreads();

    // ---- neg sums: kept negatives are the suffix of length an[i] ----
    for (int a = 0; a < APB; a++) {
        int anc  = Tl->an[a];
        int p0   = NN - anc;                       // first kept index
        int boff = Tl->aoff[a] + Tl->ap[a];        // weight base for negatives
        float local = 0.0f;
        for (int p = p0 + t; p < NN; p += NTHR) {
            float v = neg[a * NN + p];
            int wi = boff + (p - p0);
            if (wi >= wtotal) wi = wtotal - 1;
            float w = W[wi];
            local += expf(A_ALPHA * (v * w - A_BASE));
        }
        float s = block_reduce_sum(local, red);
        if (t == 0) Tl->negsum[a] = s;
        __syncthreads();
    }

    // ---- last-anchor mean negative sim (-inf padding sorted to front 8) ----
    if (blockIdx.x == NBLK - 1) {
        float local = 0.0f;
        for (int p = SPCC + t; p < NN; p += NTHR) {
            local += neg[(APB - 1) * NN + p];
        }
        float s = block_reduce_sum(local, red);
        if (t == 0) g_stats[1] = s / (float)NEGK;
    }
    __syncthreads();

    // ---- pos sums + per-anchor loss (kept positives = prefix of length ap[i]) ----
    if (t < APB) {
        int i     = i0 + t;
        int cnt   = Tl->poscnt[t];
        int apc   = Tl->ap[t];
        int anc   = Tl->an[t];
        int aoff  = Tl->aoff[t];
        int keep  = apc < cnt ? apc : cnt;
        float possum = 0.0f;
        for (int q = 0; q < keep; q++) {
            float v = Tl->pos[t][q];
            int wi = aoff + q; if (wi >= wtotal) wi = wtotal - 1;
            float w = W[wi];
            possum += expf(-A_BETA * (v * w - A_BASE));
        }
        bool has = (apc > 0) && (anc > 0);
        float li = (2.0f / A_BETA) * log1pf(possum) + (2.0f / A_ALPHA) * log1pf(Tl->negsum[t]);
        g_loss[i] = has ? li : 0.0f;
        g_cnt[i]  = has ? (apc + anc) : 0;
        if (i == NN - 1) {
            float ps = 0.0f;
            for (int q = 0; q < cnt; q++) ps += Tl->pos[t][q];
            g_stats[0] = ps / (float)cnt;
        }
    }
}

// ---------------- final reduction ----------------
__global__ void finalize_kernel(float* out) {
    __shared__ float rf[1024];
    __shared__ int   rc[1024];
    int t = threadIdx.x;
    float ls = 0.0f; int cs = 0;
    for (int idx = t; idx < NN; idx += 1024) { ls += g_loss[idx]; cs += g_cnt[idx]; }
    rf[t] = ls; rc[t] = cs;
    __syncthreads();
    for (int s = 512; s > 0; s >>= 1) {
        if (t < s) { rf[t] += rf[t + s]; rc[t] += rc[t + s]; }
        __syncthreads();
    }
    if (t == 0) {
        out[0] = rf[0] / (float)NN;
        out[1] = (float)rc[0] / (float)NN;
        out[2] = g_stats[0];
        out[3] = g_stats[1];
    }
}

extern "C" void kernel_launch(void* const* d_in, const int* in_sizes, int n_in,
                              void* d_out, int out_size)
{
    const float* X       = (const float*)d_in[0];
    const float* margin  = (const float*)d_in[1];
    const float* W       = (const float*)d_in[2];
    const int*   targets = (const int*)d_in[3];
    const int*   ap      = (const int*)d_in[4];
    const int*   an      = (const int*)d_in[5];
    int wtotal = in_sizes[2];
    float* out = (float*)d_out;

    cudaFuncSetAttribute(anchor_kernel, cudaFuncAttributeMaxDynamicSharedMemorySize, SMEM_BYTES);

    dim3 tb(32, 8);
    transpose_kernel<<<dim3(NN / 32, DD / 32), tb>>>(X);
    scan_kernel<<<1, 1024>>>(ap, an);
    anchor_kernel<<<NBLK, NTHR, SMEM_BYTES>>>(X, margin, W, targets, ap, an, wtotal);
    finalize_kernel<<<1, 1024>>>(out);
}

// round 12
// speedup vs baseline: 1.3933x; 1.3933x over previous
#include <cuda_runtime.h>
#include <math.h>

#define NN      4096
#define DD      128
#define SPCC    8
#define NEGK    (NN - SPCC)
#define APB     8            // anchors per block
#define NBLK    (NN / APB)   // 512
#define NTHR    512
#define NWARP   (NTHR / 32)  // 16
#define EPT     8            // elements per thread in the sort (NN/NTHR)
#define A_ALPHA 10.0f
#define A_BETA  2.0f
#define A_BASE  0.5f

#define NEGINF  (__int_as_float(0xff800000))

typedef unsigned long long ull;

// -------- device scratch (no dynamic allocation allowed) --------
__device__ float g_XT[DD * NN];    // transposed inputs: XT[d*NN + j] = X[j*DD + d]
__device__ float g_loss[NN];
__device__ int   g_cnt[NN];
__device__ float g_stats[2];       // [0]=mean_pos_sim, [1]=mean_neg_sim (last anchor)

struct Tail {
    float pos[APB][16];
    int   poscnt[APB];
    int   ti[APB];
    int   ap[APB];
    int   an[APB];
    int   aoff[APB];
    float negsum[APB];
};

// smem: neg[APB*NN] | xsP[DD*APB] (packed f32x2) | red[NWARP] | Tail  (~136 KB)
#define SMEM_BYTES (APB*NN*4 + DD*APB*8 + NWARP*4 + (((int)sizeof(Tail) + 127) & ~127))

// ---- f32x2 packed helpers ----
__device__ __forceinline__ ull pk2(float lo, float hi) {
    ull r; asm("mov.b64 %0, {%1, %2};" : "=l"(r) : "f"(lo), "f"(hi)); return r;
}
__device__ __forceinline__ void upk2(float& lo, float& hi, ull v) {
    asm("mov.b64 {%0, %1}, %2;" : "=f"(lo), "=f"(hi) : "l"(v));
}
__device__ __forceinline__ ull fma2(ull a, ull b, ull c) {
    ull d; asm("fma.rn.f32x2 %0, %1, %2, %3;" : "=l"(d) : "l"(a), "l"(b), "l"(c)); return d;
}

// ---------------- transpose kernel ----------------
__global__ void transpose_kernel(const float* __restrict__ X) {
    __shared__ float tile[32][33];
    int tx = threadIdx.x, ty = threadIdx.y;
    #pragma unroll
    for (int q = 0; q < 4; q++) {
        int row = ty + q * 8;                 // local j
        int j = blockIdx.x * 32 + row;
        int d = blockIdx.y * 32 + tx;
        tile[row][tx] = X[j * DD + d];
    }
    __syncthreads();
    #pragma unroll
    for (int q = 0; q < 4; q++) {
        int row = ty + q * 8;                 // local d
        int d = blockIdx.y * 32 + row;
        int j = blockIdx.x * 32 + tx;
        g_XT[d * NN + j] = tile[tx][row];
    }
}

// ---------------- shuffle-based block reduces (3 syncs) ----------------
__device__ __forceinline__ float block_reduce_sum(float v, float* red) {
    int lane = threadIdx.x & 31, w = threadIdx.x >> 5;
    #pragma unroll
    for (int s = 16; s > 0; s >>= 1) v += __shfl_xor_sync(0xffffffffu, v, s);
    if (lane == 0) red[w] = v;
    __syncthreads();
    if (w == 0) {
        float r = (lane < NWARP) ? red[lane] : 0.0f;
        #pragma unroll
        for (int s = 8; s > 0; s >>= 1) r += __shfl_xor_sync(0xffffffffu, r, s);
        if (lane == 0) red[0] = r;
    }
    __syncthreads();
    float r = red[0];
    __syncthreads();
    return r;
}
__device__ __forceinline__ int block_reduce_sum_int(int v, int* red) {
    int lane = threadIdx.x & 31, w = threadIdx.x >> 5;
    #pragma unroll
    for (int s = 16; s > 0; s >>= 1) v += __shfl_xor_sync(0xffffffffu, v, s);
    if (lane == 0) red[w] = v;
    __syncthreads();
    if (w == 0) {
        int r = (lane < NWARP) ? red[lane] : 0;
        #pragma unroll
        for (int s = 8; s > 0; s >>= 1) r += __shfl_xor_sync(0xffffffffu, r, s);
        if (lane == 0) red[0] = r;
    }
    __syncthreads();
    int r = red[0];
    __syncthreads();
    return r;
}

// compare-exchange in registers
__device__ __forceinline__ void ce(float* v, int i, int j, bool up) {
    float a = v[i], b = v[j];
    if ((a > b) == up) { v[i] = b; v[j] = a; }
}

// shuffle compare-exchange: partner lane = lane ^ s, element distance jj = 8*s
__device__ __forceinline__ void shfl_ce(float* v, int s, bool up, int lane) {
    bool lower = ((lane & s) == 0);
    #pragma unroll
    for (int r = 0; r < EPT; r++) {
        float o  = __shfl_xor_sync(0xffffffffu, v[r], s);
        float mn = fminf(v[r], o);
        float mx = fmaxf(v[r], o);
        v[r] = (lower == up) ? mn : mx;
    }
}

// ---------------- main per-anchor kernel ----------------
__global__ void __launch_bounds__(NTHR, 1)
anchor_kernel(const float* __restrict__ X, const float* __restrict__ margin,
              const float* __restrict__ W, const int* __restrict__ targets,
              const int* __restrict__ ap, const int* __restrict__ an, int wtotal)
{
    extern __shared__ char sraw[];
    float* neg = (float*)sraw;                          // APB*NN floats
    ull*   xsP = (ull*)(neg + APB * NN);                // DD*APB packed (x,x)
    float* red = (float*)(xsP + DD * APB);              // NWARP floats
    Tail*  Tl  = (Tail*)(red + NWARP);

    int t    = threadIdx.x;
    int lane = t & 31;
    int wrp  = t >> 5;
    int i0   = blockIdx.x * APB;

    if (t < APB) {
        int i = i0 + t;
        Tl->poscnt[t] = 0;
        Tl->negsum[t] = 0.0f;
        Tl->ti[t]     = targets[i];
        Tl->ap[t]     = ap[i];
        Tl->an[t]     = an[i];
    }
    // build packed anchor matrix: xsP[d*APB + a] = (x, x)
    for (int idx = t; idx < APB * DD; idx += NTHR) {
        int a = idx / DD, d = idx % DD;
        float x = X[(i0 + a) * DD + d];
        xsP[d * APB + a] = pk2(x, x);
    }

    // ---- in-block weight-offset prefix (replaces separate scan kernel) ----
    {
        int pre = 0;
        for (int idx = t; idx < i0; idx += NTHR) pre += ap[idx] + an[idx];
        int prefix = block_reduce_sum_int(pre, (int*)red);
        if (t < APB) {
            int off = prefix;
            for (int k = 0; k < APB; k++) {
                if (k == t) break;
                off += Tl->ap[k] + Tl->an[k];
            }
            Tl->aoff[t] = off;
        }
    }
    __syncthreads();

    int tis[APB];
    #pragma unroll
    for (int a = 0; a < APB; a++) tis[a] = Tl->ti[a];

    // ---- dot phase: each thread handles 2 groups of 4 contiguous j's ----
    #pragma unroll
    for (int h = 0; h < 2; h++) {
        int jb = h * (NN / 2) + t * 4;       // 16B-aligned
        ull acc2[APB][2];
        #pragma unroll
        for (int a = 0; a < APB; a++) { acc2[a][0] = 0ull; acc2[a][1] = 0ull; }

        #pragma unroll 4
        for (int d = 0; d < DD; d++) {
            float4 r4 = *(const float4*)(g_XT + d * NN + jb);   // LDG.128
            ull rlo = pk2(r4.x, r4.y);
            ull rhi = pk2(r4.z, r4.w);
            const ull* xp = xsP + d * APB;
            #pragma unroll
            for (int a = 0; a < APB; a++) {
                ull xa = xp[a];                                  // LDS broadcast
                acc2[a][0] = fma2(xa, rlo, acc2[a][0]);
                acc2[a][1] = fma2(xa, rhi, acc2[a][1]);
            }
        }

        int4 tj4 = *(const int4*)(targets + jb);
        int tja[4] = {tj4.x, tj4.y, tj4.z, tj4.w};
        #pragma unroll
        for (int a = 0; a < APB; a++) {
            float sv[4];
            upk2(sv[0], sv[1], acc2[a][0]);
            upk2(sv[2], sv[3], acc2[a][1]);
            #pragma unroll
            for (int q = 0; q < 4; q++) {
                if (tja[q] == tis[a]) {
                    float sim = sv[q];
                    sv[q] = NEGINF;
                    if (sim < 1.0f) {
                        int p = atomicAdd(&Tl->poscnt[a], 1);
                        if (p < 16) Tl->pos[a][p] = sim;
                    }
                }
            }
            *(float4*)(neg + a * NN + jb) = make_float4(sv[0], sv[1], sv[2], sv[3]);
        }
    }
    __syncthreads();

    // =========== bitonic sort (ascending): registers + warp shuffles ===========
    int base = t * EPT;                 // this thread's 8-element chunk

    // -- session A: kk = 2 .. 256 entirely in registers/shuffles --
    #pragma unroll
    for (int a = 0; a < APB; a++) {
        float* arr = neg + a * NN + base;
        float v[EPT];
        *(float4*)(v)     = *(float4*)(arr);
        *(float4*)(v + 4) = *(float4*)(arr + 4);
        // kk=2 : up = ((idx & 2) == 0)
        ce(v, 0, 1, true);  ce(v, 2, 3, false);
        ce(v, 4, 5, true);  ce(v, 6, 7, false);
        // kk=4 : up = ((idx & 4) == 0)
        ce(v, 0, 2, true);  ce(v, 1, 3, true);
        ce(v, 4, 6, false); ce(v, 5, 7, false);
        ce(v, 0, 1, true);  ce(v, 2, 3, true);
        ce(v, 4, 5, false); ce(v, 6, 7, false);
        // kk=8 : up uniform per thread
        {
            bool u8 = ((base & 8) == 0);
            ce(v, 0, 4, u8); ce(v, 1, 5, u8); ce(v, 2, 6, u8); ce(v, 3, 7, u8);
            ce(v, 0, 2, u8); ce(v, 1, 3, u8); ce(v, 4, 6, u8); ce(v, 5, 7, u8);
            ce(v, 0, 1, u8); ce(v, 2, 3, u8); ce(v, 4, 5, u8); ce(v, 6, 7, u8);
        }
        // kk = 16 .. 256 : shuffles (jj=kk/2..8) + in-register (jj=4,2,1)
        #pragma unroll
        for (int kk = 16; kk <= 256; kk <<= 1) {
            bool up = ((base & kk) == 0);
            for (int jj = kk >> 1; jj >= 8; jj >>= 1)
                shfl_ce(v, jj >> 3, up, lane);
            ce(v, 0, 4, up); ce(v, 1, 5, up); ce(v, 2, 6, up); ce(v, 3, 7, up);
            ce(v, 0, 2, up); ce(v, 1, 3, up); ce(v, 4, 6, up); ce(v, 5, 7, up);
            ce(v, 0, 1, up); ce(v, 2, 3, up); ce(v, 4, 5, up); ce(v, 6, 7, up);
        }
        *(float4*)(arr)     = *(float4*)(v);
        *(float4*)(arr + 4) = *(float4*)(v + 4);
    }
    __syncthreads();

    // -- kk = 512 .. 4096: vectorized smem passes for jj >= 256, then warp session --
    for (int kk = 512; kk <= NN; kk <<= 1) {
        for (int jj = kk >> 1; jj >= 256; jj >>= 1) {
            int lowmask = jj - 1;
            int p0  = t * 4;                                   // 4 consecutive pairs
            int idx = ((p0 & ~lowmask) << 1) | (p0 & lowmask); // 16B-aligned, no group wrap
            bool up = ((idx & kk) == 0);
            #pragma unroll
            for (int a = 0; a < APB; a++) {
                float* arr = neg + a * NN;
                float4 lo4 = *(float4*)(arr + idx);
                float4 hi4 = *(float4*)(arr + idx + jj);
                float4 nl, nh;
                if (up) {
                    nl.x = fminf(lo4.x, hi4.x); nh.x = fmaxf(lo4.x, hi4.x);
                    nl.y = fminf(lo4.y, hi4.y); nh.y = fmaxf(lo4.y, hi4.y);
                    nl.z = fminf(lo4.z, hi4.z); nh.z = fmaxf(lo4.z, hi4.z);
                    nl.w = fminf(lo4.w, hi4.w); nh.w = fmaxf(lo4.w, hi4.w);
                } else {
                    nl.x = fmaxf(lo4.x, hi4.x); nh.x = fminf(lo4.x, hi4.x);
                    nl.y = fmaxf(lo4.y, hi4.y); nh.y = fminf(lo4.y, hi4.y);
                    nl.z = fmaxf(lo4.z, hi4.z); nh.z = fminf(lo4.z, hi4.z);
                    nl.w = fmaxf(lo4.w, hi4.w); nh.w = fminf(lo4.w, hi4.w);
                }
                *(float4*)(arr + idx)      = nl;
                *(float4*)(arr + idx + jj) = nh;
            }
            __syncthreads();
        }
        // jj = 128 .. 1 inside the warp chunk (direction warp-uniform: kk >= 512)
        bool up = ((base & kk) == 0);
        #pragma unroll
        for (int a = 0; a < APB; a++) {
            float* arr = neg + a * NN + base;
            float v[EPT];
            *(float4*)(v)     = *(float4*)(arr);
            *(float4*)(v + 4) = *(float4*)(arr + 4);
            shfl_ce(v, 16, up, lane);   // jj = 128
            shfl_ce(v,  8, up, lane);   // jj = 64
            shfl_ce(v,  4, up, lane);   // jj = 32
            shfl_ce(v,  2, up, lane);   // jj = 16
            shfl_ce(v,  1, up, lane);   // jj = 8
            ce(v, 0, 4, up); ce(v, 1, 5, up); ce(v, 2, 6, up); ce(v, 3, 7, up);
            ce(v, 0, 2, up); ce(v, 1, 3, up); ce(v, 4, 6, up); ce(v, 5, 7, up);
            ce(v, 0, 1, up); ce(v, 2, 3, up); ce(v, 4, 5, up); ce(v, 6, 7, up);
            *(float4*)(arr)     = *(float4*)(v);
            *(float4*)(arr + 4) = *(float4*)(v + 4);
        }
        __syncthreads();
    }

    // ---- per-anchor: sort the (<=8, capped 16) positives ----
    if (t < APB) {
        int cnt = Tl->poscnt[t]; if (cnt > 16) cnt = 16;
        float pv[16];
        for (int q = 0; q < cnt; q++) pv[q] = Tl->pos[t][q];
        for (int q = 1; q < cnt; q++) {
            float key = pv[q]; int r = q - 1;
            while (r >= 0 && pv[r] > key) { pv[r + 1] = pv[r]; r--; }
            pv[r + 1] = key;
        }
        for (int q = 0; q < cnt; q++) Tl->pos[t][q] = pv[q];
        Tl->poscnt[t] = cnt;
    }
    __syncthreads();

    // ---- neg sums: warp-parallel (2 warps per anchor, exactly 2 atomic adders) ----
    {
        int a    = wrp & 7;            // anchor for this warp
        int half = wrp >> 3;           // 0 or 1
        int anc  = Tl->an[a];
        int p0   = NN - anc;
        int boff = Tl->aoff[a] + Tl->ap[a];
        float local = 0.0f;
        for (int p = p0 + half * 32 + lane; p < NN; p += 64) {
            float v = neg[a * NN + p];
            int wi = boff + (p - p0);
            if (wi >= wtotal) wi = wtotal - 1;
            float w = W[wi];
            local += expf(A_ALPHA * (v * w - A_BASE));
        }
        #pragma unroll
        for (int s = 16; s > 0; s >>= 1) local += __shfl_xor_sync(0xffffffffu, local, s);
        if (lane == 0) atomicAdd(&Tl->negsum[a], local);
    }
    __syncthreads();

    // ---- last-anchor mean negative sim (-inf padding sorted to front 8) ----
    if (blockIdx.x == NBLK - 1) {
        float local = 0.0f;
        for (int p = SPCC + t; p < NN; p += NTHR) {
            local += neg[(APB - 1) * NN + p];
        }
        float s = block_reduce_sum(local, red);
        if (t == 0) g_stats[1] = s / (float)NEGK;
    }
    __syncthreads();

    // ---- pos sums + per-anchor loss (kept positives = prefix of length ap[i]) ----
    if (t < APB) {
        int i     = i0 + t;
        int cnt   = Tl->poscnt[t];
        int apc   = Tl->ap[t];
        int anc   = Tl->an[t];
        int aoff  = Tl->aoff[t];
        int keep  = apc < cnt ? apc : cnt;
        float possum = 0.0f;
        for (int q = 0; q < keep; q++) {
            float v = Tl->pos[t][q];
            int wi = aoff + q; if (wi >= wtotal) wi = wtotal - 1;
            float w = W[wi];
            possum += expf(-A_BETA * (v * w - A_BASE));
        }
        bool has = (apc > 0) && (anc > 0);
        float li = (2.0f / A_BETA) * log1pf(possum) + (2.0f / A_ALPHA) * log1pf(Tl->negsum[t]);
        g_loss[i] = has ? li : 0.0f;
        g_cnt[i]  = has ? (apc + anc) : 0;
        if (i == NN - 1) {
            float ps = 0.0f;
            for (int q = 0; q < cnt; q++) ps += Tl->pos[t][q];
            g_stats[0] = ps / (float)cnt;
        }
    }
}

// ---------------- final reduction ----------------
__global__ void finalize_kernel(float* out) {
    __shared__ float rf[1024];
    __shared__ int   rc[1024];
    int t = threadIdx.x;
    float ls = 0.0f; int cs = 0;
    for (int idx = t; idx < NN; idx += 1024) { ls += g_loss[idx]; cs += g_cnt[idx]; }
    rf[t] = ls; rc[t] = cs;
    __syncthreads();
    for (int s = 512; s > 0; s >>= 1) {
        if (t < s) { rf[t] += rf[t + s]; rc[t] += rc[t + s]; }
        __syncthreads();
    }
    if (t == 0) {
        out[0] = rf[0] / (float)NN;
        out[1] = (float)rc[0] / (float)NN;
        out[2] = g_stats[0];
        out[3] = g_stats[1];
    }
}

extern "C" void kernel_launch(void* const* d_in, const int* in_sizes, int n_in,
                              void* d_out, int out_size)
{
    const float* X       = (const float*)d_in[0];
    const float* margin  = (const float*)d_in[1];
    const float* W       = (const float*)d_in[2];
    const int*   targets = (const int*)d_in[3];
    const int*   ap      = (const int*)d_in[4];
    const int*   an      = (const int*)d_in[5];
    int wtotal = in_sizes[2];
    float* out = (float*)d_out;

    cudaFuncSetAttribute(anchor_kernel, cudaFuncAttributeMaxDynamicSharedMemorySize, SMEM_BYTES);

    dim3 tb(32, 8);
    transpose_kernel<<<dim3(NN / 32, DD / 32), tb>>>(X);
    anchor_kernel<<<NBLK, NTHR, SMEM_BYTES>>>(X, margin, W, targets, ap, an, wtotal);
    finalize_kernel<<<1, 1024>>>(out);
}